// round 16
// baseline (speedup 1.0000x reference)
#include <cuda_runtime.h>
#include <cuda_bf16.h>
#include <math.h>
#include <stdint.h>

// ---------------------------------------------------------------------------
// GAT inductive net, N=4096. R15 = R14 with 3-stage cp.async GEMM mainloop
// (BK=32, single __syncthreads per K-tile, 2 groups in flight).
// Pure-bf16 1-term GEMM (validated error model: final rel ~4e-5).
// ---------------------------------------------------------------------------

#define NN 4096
#define MAXD 96

typedef __nv_bfloat16 bf16;

// ---------------- device scratch (allocation-free rule) ----------------
__device__ __align__(256) bf16  g_h[NN * 1024];
__device__ __align__(256) float g_h3[NN * 768];
__device__ __align__(256) float g_sc[28 * NN];
__device__ __align__(256) int   g_nbr[NN * MAXD];
__device__ __align__(256) int   g_deg[NN];
__device__ __align__(256) bf16 g_x0[NN * 64];
__device__ __align__(256) bf16 g_x1[NN * 1024];
__device__ __align__(256) bf16 g_x2[NN * 1024];
__device__ __align__(256) bf16 g_w1[1024 * 64];
__device__ __align__(256) bf16 g_w2[1024 * 1024];
__device__ __align__(256) bf16 g_w3[768 * 1024];

// ---------------- helpers ----------------
__device__ __forceinline__ uint32_t smem_u32(const void* p) {
    uint32_t a;
    asm("{ .reg .u64 t; cvta.to.shared.u64 t, %1; cvt.u32.u64 %0, t; }"
        : "=r"(a) : "l"(p));
    return a;
}
__device__ __forceinline__ void cp16(uint32_t dst, const void* src) {
    asm volatile("cp.async.cg.shared.global [%0], [%1], 16;"
                 :: "r"(dst), "l"(src));
}
__device__ __forceinline__ void ldsm4(uint32_t* r, uint32_t addr) {
    asm volatile("ldmatrix.sync.aligned.m8n8.x4.shared.b16 {%0,%1,%2,%3}, [%4];"
                 : "=r"(r[0]), "=r"(r[1]), "=r"(r[2]), "=r"(r[3]) : "r"(addr));
}
__device__ __forceinline__ void mma16816(float* c, const uint32_t* a,
                                         uint32_t b0, uint32_t b1) {
    asm volatile(
        "mma.sync.aligned.m16n8k16.row.col.f32.bf16.bf16.f32 "
        "{%0,%1,%2,%3}, {%4,%5,%6,%7}, {%8,%9}, {%0,%1,%2,%3};"
        : "+f"(c[0]), "+f"(c[1]), "+f"(c[2]), "+f"(c[3])
        : "r"(a[0]), "r"(a[1]), "r"(a[2]), "r"(a[3]), "r"(b0), "r"(b1));
}
__device__ __forceinline__ void unpack8(const uint4& u, float* f) {
    float2 a = __bfloat1622float2(*(const __nv_bfloat162*)&u.x);
    float2 b = __bfloat1622float2(*(const __nv_bfloat162*)&u.y);
    float2 c = __bfloat1622float2(*(const __nv_bfloat162*)&u.z);
    float2 d = __bfloat1622float2(*(const __nv_bfloat162*)&u.w);
    f[0] = a.x; f[1] = a.y; f[2] = b.x; f[3] = b.y;
    f[4] = c.x; f[5] = c.y; f[6] = d.x; f[7] = d.y;
}

// ---------------------------------------------------------------------------
// weight transpose-convert tile (32x32 via smem)
// ---------------------------------------------------------------------------
__device__ __forceinline__ void conv_tile(
    const float* __restrict__ W, bf16* __restrict__ wb,
    int Kdim, int Ndim, int Kpad, int Npad, int bx, int by, int h,
    float (*tile)[33], int t) {
    const int tx = t & 31, ty = t >> 5;
    const int n0 = bx * 32, k0 = by * 32;
    const float* Wh = W + (size_t)h * Kdim * Ndim;
#pragma unroll
    for (int j = 0; j < 4; j++) {
        int k = k0 + ty + j * 8;
        int n = n0 + tx;
        tile[ty + j * 8][tx] = (k < Kdim && n < Ndim) ? Wh[(size_t)k * Ndim + n] : 0.f;
    }
    __syncthreads();
    bf16* wp = wb + (size_t)h * Npad * Kpad;
#pragma unroll
    for (int j = 0; j < 4; j++) {
        int n = n0 + ty + j * 8;
        int k = k0 + tx;
        wp[(size_t)n * Kpad + k] = __float2bfloat16(tile[tx][ty + j * 8]);
    }
}

// ---------------------------------------------------------------------------
// ONE prep kernel: [0,512) nbr; [512,1536) x; [1536,1600) W1; [1600,2624) W2;
// [2624,3392) W3.
// ---------------------------------------------------------------------------
__global__ __launch_bounds__(256) void prep_combo(
    const int* __restrict__ adj, int* __restrict__ nbr, int* __restrict__ deg,
    const float* __restrict__ x, bf16* __restrict__ x0,
    const float* __restrict__ W1, bf16* __restrict__ w1,
    const float* __restrict__ W2, bf16* __restrict__ w2,
    const float* __restrict__ W3, bf16* __restrict__ w3) {
    __shared__ float tile[32][33];
    const int b = blockIdx.x;
    const int t = threadIdx.x;
    if (b < 512) {
        int warp = (b * 256 + t) >> 5;
        int lane = t & 31;
        const uint4* row4 = (const uint4*)(adj + (size_t)warp * NN);
        int* nrow = nbr + warp * MAXD;
        int cnt = 0;
        const unsigned lt = (1u << lane) - 1u;
        for (int base = 0; base < NN; base += 128) {
            uint4 v = row4[(base >> 2) + lane];
            unsigned b0 = __ballot_sync(0xffffffffu, v.x != 0);
            unsigned b1 = __ballot_sync(0xffffffffu, v.y != 0);
            unsigned b2 = __ballot_sync(0xffffffffu, v.z != 0);
            unsigned b3 = __ballot_sync(0xffffffffu, v.w != 0);
            int p = cnt + __popc(b0 & lt) + __popc(b1 & lt) +
                    __popc(b2 & lt) + __popc(b3 & lt);
            int e = base + lane * 4;
            if (v.x) { if (p < MAXD) nrow[p] = e;     p++; }
            if (v.y) { if (p < MAXD) nrow[p] = e + 1; p++; }
            if (v.z) { if (p < MAXD) nrow[p] = e + 2; p++; }
            if (v.w) { if (p < MAXD) nrow[p] = e + 3; p++; }
            cnt += __popc(b0) + __popc(b1) + __popc(b2) + __popc(b3);
        }
        if (lane == 0) deg[warp] = min(cnt, MAXD);
    } else if (b < 1536) {
        int i = (b - 512) * 256 + t;
        int n = i >> 6, k = i & 63;
        float v = (k < 50) ? x[n * 50 + k] : 0.f;
        x0[i] = __float2bfloat16(v);
    } else if (b < 1600) {
        int bb = b - 1536;
        conv_tile(W1, w1, 50, 256, 64, 256,
                  bb & 7, (bb >> 3) & 1, bb >> 4, tile, t);
    } else if (b < 2624) {
        int bb = b - 1600;
        conv_tile(W2, w2, 1024, 256, 1024, 256,
                  bb & 7, (bb >> 3) & 31, bb >> 8, tile, t);
    } else {
        int bb = b - 2624;
        conv_tile(W3, w3, 1024, 121, 1024, 128,
                  bb & 3, (bb >> 2) & 31, bb >> 7, tile, t);
    }
}

// ---------------------------------------------------------------------------
// 1-term bf16 GEMM, 3-stage cp.async pipeline, fused score epilogue.
// C[4096][NT] = A[4096,K] * B[NT,K]^T ; BK=32, one __syncthreads per K-tile.
// ---------------------------------------------------------------------------
#define TSTRIDE 40
#define ROWB    (TSTRIDE * 2)          // 80 B per smem row
#define MAT_A   (128 * ROWB)           // 10240 B

template <int BN, int HS, int FD, bool CBF16>
__global__ __launch_bounds__(256, 2) void gemm_mma(
    const bf16* __restrict__ A, const bf16* __restrict__ B,
    void* __restrict__ Cv, float* __restrict__ es, float* __restrict__ ed,
    const float* __restrict__ asrc, const float* __restrict__ adst,
    int K, int NT) {
    constexpr int MAT_B = BN * ROWB;
    constexpr int STG   = MAT_A + MAT_B;
    constexpr int BNP   = BN / 32;

    extern __shared__ __align__(16) char smem[];
    const uint32_t sbase = smem_u32(smem);
    const int tid  = threadIdx.x;
    const int lane = tid & 31;
    const int wid  = tid >> 5;
    const int wm   = wid & 3;
    const int wn   = wid >> 2;
    const int row0 = blockIdx.x * 128;
    const int col0 = blockIdx.y * BN;

    const bf16* gA = A + (size_t)row0 * K;
    const bf16* gB = B + (size_t)col0 * K;

    const int lrow = lane & 7, lq = lane >> 3;
    const int frow = (lq & 1) * 8 + lrow;
    const int fcol = (lq >> 1) * 8;

    float acc[2][2 * BNP][4];
#pragma unroll
    for (int i = 0; i < 2; i++)
#pragma unroll
        for (int j = 0; j < 2 * BNP; j++)
#pragma unroll
            for (int q = 0; q < 4; q++) acc[i][j][q] = 0.f;

    const int nk = K >> 5;   // BK = 32

    auto copy_stage = [&](int s, int kt) {
        const int c0 = kt * 32;
        const uint32_t bufs = sbase + s * STG;
        // A tile: 128 rows x 4 quads (16B each) -> 2 per thread
#pragma unroll
        for (int j = 0; j < 2; j++) {
            int u = tid + j * 256;
            int r = u >> 2, q = u & 3;
            cp16(bufs + r * ROWB + q * 16, gA + (size_t)r * K + c0 + q * 8);
        }
        // B tile: BN rows x 4 quads
        for (int u = tid; u < BN * 4; u += 256) {
            int r = u >> 2, q = u & 3;
            cp16(bufs + MAT_A + r * ROWB + q * 16, gB + (size_t)r * K + c0 + q * 8);
        }
    };

    // prologue: stages 0,1 in flight
    copy_stage(0, 0);
    asm volatile("cp.async.commit_group;" ::: "memory");
    if (nk > 1) {
        copy_stage(1, 1);
        asm volatile("cp.async.commit_group;" ::: "memory");
    }

    int cur = 0;
    for (int kt = 0; kt < nk; kt++) {
        // stage kt must be complete (allow 1 outstanding: stage kt+1)
        if (kt + 1 < nk) {
            asm volatile("cp.async.wait_group 1;" ::: "memory");
        } else {
            asm volatile("cp.async.wait_group 0;" ::: "memory");
        }
        __syncthreads();   // publishes stage kt; retires compute of kt-1

        // issue copy for stage kt+2 into the buffer freed at kt-1
        if (kt + 2 < nk) {
            int nx = cur + 2;
            if (nx >= 3) nx -= 3;
            copy_stage(nx, kt + 2);
            asm volatile("cp.async.commit_group;" ::: "memory");
        }

        const uint32_t bufs = sbase + cur * STG;
#pragma unroll
        for (int ks = 0; ks < 2; ks++) {
            uint32_t ah[2][4];
#pragma unroll
            for (int am = 0; am < 2; am++) {
                uint32_t off = (wm * 32 + am * 16 + frow) * ROWB +
                               (ks * 16 + fcol) * 2;
                ldsm4(ah[am], bufs + off);
            }
#pragma unroll
            for (int bn = 0; bn < BNP; bn++) {
                uint32_t off = (wn * (BN / 2) + bn * 16 + frow) * ROWB +
                               (ks * 16 + fcol) * 2;
                uint32_t bh[4];
                ldsm4(bh, bufs + MAT_A + off);
#pragma unroll
                for (int am = 0; am < 2; am++) {
                    mma16816(acc[am][bn * 2],     ah[am], bh[0], bh[2]);
                    mma16816(acc[am][bn * 2 + 1], ah[am], bh[1], bh[3]);
                }
            }
        }
        cur++;
        if (cur >= 3) cur -= 3;
    }

    // ---- fused epilogue: store C (+ fp32-exact attention scores) ----
    const int rbase = row0 + wm * 32 + (lane >> 2);
    const int cbase = col0 + wn * (BN / 2) + (lane & 3) * 2;
    float se[2][2] = {{0.f, 0.f}, {0.f, 0.f}};
    float sd[2][2] = {{0.f, 0.f}, {0.f, 0.f}};
    int curh = cbase / HS;

    auto flush = [&](int h) {
#pragma unroll
        for (int am = 0; am < 2; am++)
#pragma unroll
            for (int sr = 0; sr < 2; sr++) {
                float v = se[am][sr];
                v += __shfl_xor_sync(0xffffffffu, v, 1);
                v += __shfl_xor_sync(0xffffffffu, v, 2);
                float u = sd[am][sr];
                u += __shfl_xor_sync(0xffffffffu, u, 1);
                u += __shfl_xor_sync(0xffffffffu, u, 2);
                if ((lane & 3) == 0) {
                    int r = rbase + am * 16 + sr * 8;
                    atomicAdd(es + h * NN + r, v);
                    atomicAdd(ed + h * NN + r, u);
                }
                se[am][sr] = 0.f;
                sd[am][sr] = 0.f;
            }
    };

#pragma unroll
    for (int na = 0; na < 2 * BNP; na++) {
        int c = cbase + na * 8;
        int hh = c / HS;
        if (hh != curh) { flush(curh); curh = hh; }
        int o = c - hh * HS;
        float as0 = (o < FD) ? asrc[hh * FD + o] : 0.f;
        float as1 = (o + 1 < FD) ? asrc[hh * FD + o + 1] : 0.f;
        float ad0 = (o < FD) ? adst[hh * FD + o] : 0.f;
        float ad1 = (o + 1 < FD) ? adst[hh * FD + o + 1] : 0.f;
#pragma unroll
        for (int am = 0; am < 2; am++) {
            float* a4 = acc[am][na];
            se[am][0] += a4[0] * as0 + a4[1] * as1;
            se[am][1] += a4[2] * as0 + a4[3] * as1;
            sd[am][0] += a4[0] * ad0 + a4[1] * ad1;
            sd[am][1] += a4[2] * ad0 + a4[3] * ad1;
            int r = rbase + am * 16;
            if (CBF16) {
                bf16* Cb = (bf16*)Cv;
                float2 v0 = {a4[0], a4[1]};
                float2 v1 = {a4[2], a4[3]};
                *(__nv_bfloat162*)(Cb + (size_t)r * NT + c) = __float22bfloat162_rn(v0);
                *(__nv_bfloat162*)(Cb + (size_t)(r + 8) * NT + c) = __float22bfloat162_rn(v1);
            } else {
                float* Cf = (float*)Cv;
                float2 v0 = {a4[0], a4[1]};
                float2 v1 = {a4[2], a4[3]};
                *(float2*)(Cf + (size_t)r * NT + c) = v0;
                *(float2*)(Cf + (size_t)(r + 8) * NT + c) = v1;
            }
        }
    }
    flush(curh);
}

// ---------------------------------------------------------------------------
// agg12 v2: TWO nodes per block, 256 threads. bf16 in, bf16 out.
// ---------------------------------------------------------------------------
__global__ __launch_bounds__(256) void agg12_kernel(
    const bf16* __restrict__ hbuf, const float* __restrict__ es,
    const float* __restrict__ ed, const int* __restrict__ nbr,
    const int* __restrict__ deg,
    const bf16* __restrict__ prev, bf16* __restrict__ outb) {
    const int n0 = blockIdx.x * 2;
    const int t = threadIdx.x;
    const int lane = t & 31, w = t >> 5;
    __shared__ int   s_nbr[2][MAXD];
    __shared__ __align__(16) float s_alpha[2][4][MAXD];
    __shared__ float s_inv[2][4];
    __shared__ int   s_deg[2];

    if (t < MAXD) s_nbr[0][t] = nbr[n0 * MAXD + t];
    else if (t >= 128 && t < 128 + MAXD)
        s_nbr[1][t - 128] = nbr[(n0 + 1) * MAXD + (t - 128)];
    if (t == 224) s_deg[0] = deg[n0];
    if (t == 225) s_deg[1] = deg[n0 + 1];
    __syncthreads();

    {   // softmax alpha: warp w -> (node w>>2, head w&3)
        const int nd = w >> 2, hh = w & 3;
        const int d = s_deg[nd];
        const float es_n = es[hh * NN + n0 + nd];
        float mx = -1e30f;
        for (int i = lane; i < d; i += 32) {
            float e = es_n + ed[hh * NN + s_nbr[nd][i]];
            e = (e > 0.f) ? e : 0.2f * e;
            s_alpha[nd][hh][i] = e;
            mx = fmaxf(mx, e);
        }
#pragma unroll
        for (int off = 16; off; off >>= 1) mx = fmaxf(mx, __shfl_xor_sync(0xffffffffu, mx, off));
        float sum = 0.f;
        for (int i = lane; i < d; i += 32) {
            float a = expf(s_alpha[nd][hh][i] - mx);
            s_alpha[nd][hh][i] = a;
            sum += a;
        }
#pragma unroll
        for (int off = 16; off; off >>= 1) sum += __shfl_xor_sync(0xffffffffu, sum, off);
        if (lane == 0) s_inv[nd][hh] = 1.f / sum;
    }
    __syncthreads();

    const int nd  = t >> 7;
    const int col = (t & 127) * 8;
    const int hh  = (t & 127) >> 5;
    const int d   = s_deg[nd];
    const bf16* hb = hbuf + col;
    const float* al = s_alpha[nd][hh];
    const int* nb = s_nbr[nd];

    float acc[8];
#pragma unroll
    for (int j = 0; j < 8; j++) acc[j] = 0.f;

    int i = 0;
    for (; i + 1 < d; i += 2) {
        uint4 u0 = *(const uint4*)(hb + (size_t)nb[i] * 1024);
        uint4 u1 = *(const uint4*)(hb + (size_t)nb[i + 1] * 1024);
        float a0 = al[i], a1 = al[i + 1];
        float f0[8], f1[8];
        unpack8(u0, f0);
        unpack8(u1, f1);
#pragma unroll
        for (int j = 0; j < 8; j++) acc[j] += a0 * f0[j] + a1 * f1[j];
    }
    if (i < d) {
        uint4 u0 = *(const uint4*)(hb + (size_t)nb[i] * 1024);
        float a0 = al[i];
        float f0[8];
        unpack8(u0, f0);
#pragma unroll
        for (int j = 0; j < 8; j++) acc[j] += a0 * f0[j];
    }

    const float inv = s_inv[nd][hh];
#pragma unroll
    for (int j = 0; j < 8; j++) {
        float v = acc[j] * inv;
        acc[j] = (v > 0.f) ? v : expm1f(v);       // elu
    }

    const size_t base = (size_t)(n0 + nd) * 1024 + col;
    if (prev) {
        uint4 up = *(const uint4*)(prev + base);
        float fp[8];
        unpack8(up, fp);
#pragma unroll
        for (int j = 0; j < 8; j++) acc[j] += fp[j];
    }

    uint4 uo;
#pragma unroll
    for (int j = 0; j < 4; j++) {
        float2 p = {acc[2 * j], acc[2 * j + 1]};
        __nv_bfloat162 hb2 = __float22bfloat162_rn(p);
        ((uint32_t*)&uo)[j] = *(uint32_t*)&hb2;
    }
    *(uint4*)(outb + base) = uo;
}

// ---------------------------------------------------------------------------
// Layer-3 aggregation + head-mean + log_softmax, fused. 192 threads.
// ---------------------------------------------------------------------------
__global__ __launch_bounds__(192) void agg3_final_kernel(
    const float* __restrict__ hbuf, const float* __restrict__ es,
    const float* __restrict__ ed, const int* __restrict__ nbr,
    const int* __restrict__ deg, float* __restrict__ out) {
    const int n = blockIdx.x;
    const int t = threadIdx.x;
    const int lane = t & 31, w = t >> 5;
    __shared__ __align__(16) float s_val[768];
    __shared__ __align__(16) float s_alpha[6][MAXD];
    __shared__ int   s_nbr[MAXD];
    __shared__ float s_inv[6];
    __shared__ float sv[128];
    __shared__ float s_max, s_lse;

    const int d = deg[n];
    if (t < d) s_nbr[t] = nbr[n * MAXD + t];
    __syncthreads();
    {
        const float es_n = es[w * NN + n];
        float mx = -1e30f;
        for (int i = lane; i < d; i += 32) {
            float e = es_n + ed[w * NN + s_nbr[i]];
            e = (e > 0.f) ? e : 0.2f * e;
            s_alpha[w][i] = e;
            mx = fmaxf(mx, e);
        }
#pragma unroll
        for (int off = 16; off; off >>= 1) mx = fmaxf(mx, __shfl_xor_sync(0xffffffffu, mx, off));
        float sum = 0.f;
        for (int i = lane; i < d; i += 32) {
            float a = expf(s_alpha[w][i] - mx);
            s_alpha[w][i] = a;
            sum += a;
        }
#pragma unroll
        for (int off = 16; off; off >>= 1) sum += __shfl_xor_sync(0xffffffffu, sum, off);
        if (lane == 0) s_inv[w] = 1.f / sum;
    }
    __syncthreads();

    const int o = lane * 4;
    const float* hb = hbuf + w * 128 + o;
    float4 acc = {0.f, 0.f, 0.f, 0.f};
    const float* al = s_alpha[w];
    int i = 0;
    for (; i + 3 < d; i += 4) {
        float a0 = al[i], a1 = al[i + 1], a2 = al[i + 2], a3 = al[i + 3];
        float4 v0 = *(const float4*)(hb + (size_t)s_nbr[i] * 768);
        float4 v1 = *(const float4*)(hb + (size_t)s_nbr[i + 1] * 768);
        float4 v2 = *(const float4*)(hb + (size_t)s_nbr[i + 2] * 768);
        float4 v3 = *(const float4*)(hb + (size_t)s_nbr[i + 3] * 768);
        acc.x += a0 * v0.x + a1 * v1.x + a2 * v2.x + a3 * v3.x;
        acc.y += a0 * v0.y + a1 * v1.y + a2 * v2.y + a3 * v3.y;
        acc.z += a0 * v0.z + a1 * v1.z + a2 * v2.z + a3 * v3.z;
        acc.w += a0 * v0.w + a1 * v1.w + a2 * v2.w + a3 * v3.w;
    }
    for (; i < d; i++) {
        float a0 = al[i];
        float4 v0 = *(const float4*)(hb + (size_t)s_nbr[i] * 768);
        acc.x += a0 * v0.x; acc.y += a0 * v0.y; acc.z += a0 * v0.z; acc.w += a0 * v0.w;
    }
    const float inv = s_inv[w];
    acc.x *= inv; acc.y *= inv; acc.z *= inv; acc.w *= inv;
    *(float4*)(s_val + w * 128 + o) = acc;
    __syncthreads();

    if (t < 128) {
        float v = 0.f;
#pragma unroll
        for (int h = 0; h < 6; h++) v += s_val[h * 128 + t];
        sv[t] = v * (1.f / 6.f);
    }
    __syncthreads();
    if (t < 32) {
        float mx = -1e30f;
        for (int c = t; c < 121; c += 32) mx = fmaxf(mx, sv[c]);
#pragma unroll
        for (int off = 16; off; off >>= 1) mx = fmaxf(mx, __shfl_xor_sync(0xffffffffu, mx, off));
        float sum = 0.f;
        for (int c = t; c < 121; c += 32) sum += expf(sv[c] - mx);
#pragma unroll
        for (int off = 16; off; off >>= 1) sum += __shfl_xor_sync(0xffffffffu, sum, off);
        if (t == 0) { s_max = mx; s_lse = logf(sum); }
    }
    __syncthreads();
    if (t < 121)
        out[(size_t)n * 121 + t] = sv[t] - s_max - s_lse;
}

// ---------------------------------------------------------------------------
extern "C" void kernel_launch(void* const* d_in, const int* in_sizes, int n_in,
                              void* d_out, int out_size) {
    (void)in_sizes; (void)n_in; (void)out_size;
    const float* x   = (const float*)d_in[0];
    const int*   adj = (const int*)  d_in[1];
    const float* W1  = (const float*)d_in[2];
    const float* a1s = (const float*)d_in[3];
    const float* a1d = (const float*)d_in[4];
    const float* W2  = (const float*)d_in[5];
    const float* a2s = (const float*)d_in[6];
    const float* a2d = (const float*)d_in[7];
    const float* W3  = (const float*)d_in[8];
    const float* a3s = (const float*)d_in[9];
    const float* a3d = (const float*)d_in[10];
    float* out = (float*)d_out;

    bf16 *p_h, *p_x0, *p_x1, *p_x2, *p_w1, *p_w2, *p_w3;
    float *p_h3, *p_sc;
    int *p_nbr, *p_deg;
    cudaGetSymbolAddress((void**)&p_h,   g_h);
    cudaGetSymbolAddress((void**)&p_h3,  g_h3);
    cudaGetSymbolAddress((void**)&p_sc,  g_sc);
    cudaGetSymbolAddress((void**)&p_nbr, g_nbr);
    cudaGetSymbolAddress((void**)&p_deg, g_deg);
    cudaGetSymbolAddress((void**)&p_x0,  g_x0);
    cudaGetSymbolAddress((void**)&p_x1,  g_x1);
    cudaGetSymbolAddress((void**)&p_x2,  g_x2);
    cudaGetSymbolAddress((void**)&p_w1,  g_w1);
    cudaGetSymbolAddress((void**)&p_w2,  g_w2);
    cudaGetSymbolAddress((void**)&p_w3,  g_w3);

    float* es1 = p_sc;
    float* ed1 = p_sc + 4 * NN;
    float* es2 = p_sc + 8 * NN;
    float* ed2 = p_sc + 12 * NN;
    float* es3 = p_sc + 16 * NN;
    float* ed3 = p_sc + 22 * NN;

    const int SMEM128 = 3 * (MAT_A + 128 * ROWB);   // 61440
    const int SMEM96  = 3 * (MAT_A + 96 * ROWB);    // 53760
    cudaFuncSetAttribute(gemm_mma<128, 256, 256, true>,
                         cudaFuncAttributeMaxDynamicSharedMemorySize, SMEM128);
    cudaFuncSetAttribute(gemm_mma<96, 128, 121, false>,
                         cudaFuncAttributeMaxDynamicSharedMemorySize, SMEM96);

    cudaMemsetAsync(p_sc, 0, 28 * NN * sizeof(float));

    // #1: ALL prep (nbr + x convert + W1/W2/W3 transpose-converts)
    prep_combo<<<3392, 256>>>(adj, p_nbr, p_deg, x, p_x0,
                              W1, p_w1, W2, p_w2, W3, p_w3);

    // #2 gemm1, #3 agg1, #4 gemm2 (profiler target), #5 agg2, #6 gemm3, #7 agg3
    gemm_mma<128, 256, 256, true><<<dim3(NN / 128, 8), 256, SMEM128>>>(
        p_x0, p_w1, p_h, es1, ed1, a1s, a1d, 64, 1024);
    agg12_kernel<<<NN / 2, 256>>>(p_h, es1, ed1, p_nbr, p_deg, nullptr, p_x1);

    gemm_mma<128, 256, 256, true><<<dim3(NN / 128, 8), 256, SMEM128>>>(
        p_x1, p_w2, p_h, es2, ed2, a2s, a2d, 1024, 1024);
    agg12_kernel<<<NN / 2, 256>>>(p_h, es2, ed2, p_nbr, p_deg, p_x1, p_x2);

    gemm_mma<96, 128, 121, false><<<dim3(NN / 128, 8), 256, SMEM96>>>(
        p_x2, p_w3, p_h3, es3, ed3, a3s, a3d, 1024, 768);
    agg3_final_kernel<<<NN, 192>>>(p_h3, es3, ed3, p_nbr, p_deg, out);
}